// round 13
// baseline (speedup 1.0000x reference)
#include <cuda_runtime.h>
#include <cuda_bf16.h>

#define BB    16
#define MM    256
#define NN    8192
#define NFG   128
#define NBG   384
#define SAMP  512
#define NBINS 256
#define LISTCAP 2048
#define NCTA  512
#define NTHR  256

__device__ unsigned g_keyFg[BB * NN];          // f2s(pri) if fg else 0
__device__ unsigned g_keyBg[BB * NN];          // f2s(pri) if bg else 0
__device__ unsigned g_hist[2 * BB * NBINS];    // [side][b][bin]; zeroed by sampler
__device__ unsigned g_cnt[BB];                 // per-batch arrival counters (monotone)

static __device__ __forceinline__ unsigned f2s(float f) {
    unsigned u = __float_as_uint(f);
    return (u & 0x80000000u) ? ~u : (u | 0x80000000u);
}

#define GBAR(id) asm volatile("bar.sync %0, 128;" :: "r"(id) : "memory")

__global__ __launch_bounds__(NTHR, 4)
void fused_kernel(const float4* __restrict__ gt,
                  const float4* __restrict__ prop,
                  const float*  __restrict__ pri,
                  const int*    __restrict__ gtc,
                  float* __restrict__ mv,
                  float* __restrict__ mi,
                  float* __restrict__ s_idx,
                  float* __restrict__ s_cls,
                  float* __restrict__ s_gt) {
    __shared__ float4 g[MM];
    __shared__ float  ga[MM];
    __shared__ unsigned long long list2[2][LISTCAP];
    __shared__ unsigned warpsum2[2][4];
    __shared__ int s_cnt[2], s_T[2], s_tot[2];
    __shared__ unsigned sh_ticket;

    const int tid = threadIdx.x;                 // 256
    const int c   = blockIdx.x;                  // 512
    const int lane = tid & 31;
    const int wid  = tid >> 5;
    const int b    = c >> 5;                     // batch
    const int q    = c & 31;                     // 256-proposal slice

    // ======== Phase 1: match (32 CTAs per batch, 1 proposal/thread) =========
    {
        {
            float4 v = gt[b * MM + tid];
            g[tid] = v;
            ga[tid] = __fmul_rn(v.z - v.x, v.w - v.y);
        }
        __syncthreads();

        const int n0 = b * NN + q * 256 + tid;
        float4 p0 = prop[n0];
        float pr0 = pri[n0];
        float ap0 = __fmul_rn(p0.z - p0.x, p0.w - p0.y);

        float bI = -1.0f, bU = 1.0f;
        int bx = 0;

#pragma unroll 4
        for (int m = 0; m < MM; ++m) {
            float4 gb = g[m];
            float a = ga[m];
            float lx = fmaxf(gb.x, p0.x), ly = fmaxf(gb.y, p0.y);
            float rx = fminf(gb.z, p0.z), ry = fminf(gb.w, p0.w);
            float w = fmaxf(rx - lx, 0.0f), h = fmaxf(ry - ly, 0.0f);
            float inter = __fmul_rn(w, h);
            float uni = __fsub_rn(__fadd_rn(a, ap0), inter);
            if (__fmul_rn(inter, bU) > __fmul_rn(bI, uni)) {
                bI = inter; bU = uni; bx = m;
            }
        }

        float v0 = __fdiv_rn(bI, bU);
        mv[n0] = v0;
        mi[n0] = (float)bx;
        bool fg0 = (v0 >= 0.5f);
        unsigned u0 = f2s(pr0);
        unsigned bn0 = (unsigned)(pr0 * 256.0f); if (bn0 > 255u) bn0 = 255u;
        g_keyFg[n0] = fg0 ? u0 : 0u;
        g_keyBg[n0] = fg0 ? 0u : u0;
        atomicAdd(&g_hist[(fg0 ? 0 : 1) * BB * NBINS + b * NBINS + bn0], 1u);
    }

    // ============ Phase 2: per-batch arrival; last arriver samples ==========
    __syncthreads();                              // all phase-1 work done (CTA)
    if (tid == 0) {
        __threadfence();                          // release this CTA's writes
        unsigned t = atomicAdd(&g_cnt[b], 1u);
        __threadfence();                          // acquire others' writes
        sh_ticket = t & 31u;
    }
    __syncthreads();
    if (sh_ticket != 31u) return;                 // not last => exit, no spin

    // ===== Phase 3: this CTA samples batch b. warps 0-3: fg, 4-7: bg ========
    const int  gid   = wid >> 2;                  // 0 = fg group, 1 = bg group
    const int  gtid  = tid & 127;                 // 0..127 within group
    const int  gwid  = wid & 3;                   // warp index within group
    const bool wantFg = (gid == 0);
    const int  K    = wantFg ? NFG : NBG;
    const int  off  = wantFg ? 0   : NFG;
    const int  barid = gid + 1;

    const unsigned* keys = (wantFg ? g_keyFg : g_keyBg) + b * NN;
    unsigned* histSlice = &g_hist[gid * BB * NBINS + b * NBINS];

    // Group's warp 0: suffix-scan histogram -> T, total; then zero the slice
    if (gwid == 0) {
        if (lane == 0) s_cnt[gid] = 0;
        unsigned h[8];
#pragma unroll
        for (int e = 0; e < 8; ++e) h[e] = histSlice[lane * 8 + e];
#pragma unroll
        for (int e = 0; e < 8; ++e) histSlice[lane * 8 + e] = 0u;  // for next replay
        unsigned lsum = 0;
#pragma unroll
        for (int e = 0; e < 8; ++e) lsum += h[e];
        unsigned s = lsum;
#pragma unroll
        for (int d = 1; d < 32; d <<= 1) {
            unsigned v = __shfl_down_sync(0xffffffffu, s, d);
            if (lane + d < 32) s += v;
        }
        unsigned total = __shfl_sync(0xffffffffu, s, 0);
        unsigned run = s - lsum;                  // suffix over lanes > lane
        int myT = 0;
#pragma unroll
        for (int e = 7; e >= 0; --e) {
            unsigned sufE = run + h[e];
            if ((int)sufE >= K && (int)run < K) myT = lane * 8 + e;
            run = sufE;
        }
#pragma unroll
        for (int d = 1; d < 32; d <<= 1) {
            int v = __shfl_xor_sync(0xffffffffu, myT, d);
            if (v > myT) myT = v;
        }
        if (lane == 0) { s_T[gid] = myT; s_tot[gid] = (int)total; }
    }
    GBAR(barid);

    const int T = s_T[gid];
    const int total = s_tot[gid];
    const uint4* k4 = (const uint4*)(keys + gtid * 64);   // 64 keys/thread

    // Pass A: stream keys; build 64-bit take/zero masks
    unsigned long long takemask = 0ull, zeromask = 0ull;
#pragma unroll 4
    for (int e4 = 0; e4 < 16; ++e4) {
        uint4 a = k4[e4];
        unsigned uu[4] = {a.x, a.y, a.z, a.w};
#pragma unroll
        for (int v = 0; v < 4; ++v) {
            int e = e4 * 4 + v;
            unsigned ue = uu[v];
            if (ue == 0u) zeromask |= 1ull << e;
            else {
                float p = __uint_as_float(ue ^ 0x80000000u);
                unsigned bn = (unsigned)(p * 256.0f); if (bn > 255u) bn = 255u;
                if ((int)bn >= T) takemask |= 1ull << e;
            }
        }
    }

    // Compaction: one shared atomic per warp; re-stream keys for values
    {
        unsigned cnt = 0;
#pragma unroll
        for (int e = 0; e < 64; ++e)
            cnt += __popc(__ballot_sync(0xffffffffu, (takemask >> e) & 1ull));
        int base = 0;
        if (lane == 0 && cnt) base = atomicAdd(&s_cnt[gid], (int)cnt);
        base = __shfl_sync(0xffffffffu, base, 0);
        unsigned pre = 0;
        const unsigned lmask = (lane == 0) ? 0u : (0xffffffffu >> (32 - lane));
#pragma unroll 4
        for (int e4 = 0; e4 < 16; ++e4) {
            uint4 a = k4[e4];
            unsigned uu[4] = {a.x, a.y, a.z, a.w};
#pragma unroll
            for (int v = 0; v < 4; ++v) {
                int e = e4 * 4 + v;
                unsigned ball = __ballot_sync(0xffffffffu, (takemask >> e) & 1ull);
                if ((takemask >> e) & 1ull) {
                    int pos = base + (int)pre + __popc(ball & lmask);
                    if (pos < LISTCAP) {
                        unsigned t = (unsigned)(gtid * 64 + e);
                        list2[gid][pos] = ((unsigned long long)uu[v] << 32) |
                                          (unsigned long long)(0xFFFFFFFFu - t);
                    }
                }
                pre += __popc(ball);
            }
        }
    }
    GBAR(barid);

    // Exact ranking over all candidates of this side
    {
        int S = s_cnt[gid] < LISTCAP ? s_cnt[gid] : LISTCAP;
        for (int i = gtid; i < S; i += 128) {
            unsigned long long ki = list2[gid][i];
            int rank = 0;
            for (int j = 0; j < S; ++j) rank += (list2[gid][j] > ki);
            if (rank < K) {
                int idx = (int)(0xFFFFFFFFu - (unsigned)(ki & 0xFFFFFFFFull));
                int midx = (int)mi[b * NN + idx];
                s_idx[b * SAMP + off + rank] = (float)idx;
                s_gt [b * SAMP + off + rank] = (float)midx;
                s_cls[b * SAMP + off + rank] = wantFg ? (float)gtc[b * MM + midx] : 80.0f;
            }
        }
    }

    // Fill tail (total < K) with not-selected indices, ascending
    if (total < K) {
        const int need = K - total;
        int cc = __popcll(zeromask);
        int inc = cc;
#pragma unroll
        for (int d = 1; d < 32; d <<= 1) {
            int v = __shfl_up_sync(0xffffffffu, inc, d);
            if (lane >= d) inc += v;
        }
        if (lane == 31) warpsum2[gid][gwid] = (unsigned)inc;
        GBAR(barid);
        if (gwid == 0 && lane < 4) {
            int wv = (int)warpsum2[gid][lane];
            int winc = wv;
#pragma unroll
            for (int d = 1; d < 4; d <<= 1) {
                int v = __shfl_up_sync(0xfu, winc, d);
                if (lane >= d) winc += v;
            }
            warpsum2[gid][lane] = (unsigned)(winc - wv);
        }
        GBAR(barid);
        int p = (int)warpsum2[gid][gwid] + (inc - cc);
        const int base_e = gtid * 64;
        for (int e = 0; e < 64; ++e) {
            if ((zeromask >> e) & 1ull) {
                if (p < need) {
                    int slot = b * SAMP + off + total + p;
                    s_idx[slot] = (float)(base_e + e);
                    s_cls[slot] = -1.0f;
                    s_gt [slot] = -1.0f;
                }
                ++p;
            }
        }
    }
}

extern "C" void kernel_launch(void* const* d_in, const int* in_sizes, int n_in,
                              void* d_out, int out_size) {
    const float* gt_boxes   = (const float*)d_in[0];   // [B,M,4]
    const int*   gt_classes = (const int*)  d_in[1];   // [B,M]
    const float* prop_boxes = (const float*)d_in[2];   // [B,N,4]
    const float* rand_pri   = (const float*)d_in[3];   // [B,N]

    float* out = (float*)d_out;
    float* matched_vals = out;                        // B*N
    float* matched_idxs = out + BB * NN;              // B*N
    float* sampled_idxs = out + 2 * BB * NN;          // B*512
    float* sampled_cls  = sampled_idxs + BB * SAMP;   // B*512
    float* sampled_gt   = sampled_cls  + BB * SAMP;   // B*512

    fused_kernel<<<NCTA, NTHR>>>((const float4*)gt_boxes,
                                 (const float4*)prop_boxes,
                                 rand_pri, gt_classes,
                                 matched_vals, matched_idxs,
                                 sampled_idxs, sampled_cls, sampled_gt);
}

// round 14
// speedup vs baseline: 1.6348x; 1.6348x over previous
#include <cuda_runtime.h>
#include <cuda_bf16.h>

#define BB    16
#define MM    256
#define NN    8192
#define NFG   128
#define NBG   384
#define SAMP  512
#define NBINS 256
#define LISTCAP 2048
#define NCTA  256
#define NTHR  256

__device__ unsigned g_keyFg[BB * NN];          // f2s(pri) if fg else 0
__device__ unsigned g_keyBg[BB * NN];          // f2s(pri) if bg else 0
__device__ unsigned g_hist[2 * BB * NBINS];    // [side][b][bin]; zeroed in phase3
__device__ unsigned g_arrive;                  // monotone grid-barrier counter

static __device__ __forceinline__ unsigned f2s(float f) {
    unsigned u = __float_as_uint(f);
    return (u & 0x80000000u) ? ~u : (u | 0x80000000u);
}

__global__ __launch_bounds__(NTHR, 3)
void fused_kernel(const float4* __restrict__ gt,
                  const float4* __restrict__ prop,
                  const float*  __restrict__ pri,
                  const int*    __restrict__ gtc,
                  float* __restrict__ mv,
                  float* __restrict__ mi,
                  float* __restrict__ s_idx,
                  float* __restrict__ s_cls,
                  float* __restrict__ s_gt) {
    __shared__ float4 g[MM];
    __shared__ unsigned long long list[LISTCAP];
    __shared__ unsigned warpsum[8];
    __shared__ int listCnt, sh_T, sh_total;

    const int tid = threadIdx.x;                 // 256
    const int c   = blockIdx.x;                  // 256
    const int lane = tid & 31;
    const int wid  = tid >> 5;

    // ====== Phase 1: match (16 CTAs/batch, 2 props/thread, area recomputed) ==
    {
        const int b = c >> 4;                    // batch
        const int q = c & 15;                    // 512-proposal slice
        g[tid] = gt[b * MM + tid];
        __syncthreads();

        const int n0 = b * NN + q * 512 + tid;
        const int n1 = n0 + 256;
        float4 p0 = prop[n0];
        float4 p1 = prop[n1];
        float pr0 = pri[n0];
        float pr1 = pri[n1];
        float ap0 = __fmul_rn(p0.z - p0.x, p0.w - p0.y);
        float ap1 = __fmul_rn(p1.z - p1.x, p1.w - p1.y);

        float bI0 = -1.0f, bU0 = 1.0f, bI1 = -1.0f, bU1 = 1.0f;
        int bx0 = 0, bx1 = 0;

#pragma unroll 4
        for (int m = 0; m < MM; ++m) {
            float4 gb = g[m];                    // one LDS.128 serves 2 pairs
            float a = __fmul_rn(gb.z - gb.x, gb.w - gb.y);   // recompute: no 2nd LDS
            {
                float lx = fmaxf(gb.x, p0.x), ly = fmaxf(gb.y, p0.y);
                float rx = fminf(gb.z, p0.z), ry = fminf(gb.w, p0.w);
                float w = fmaxf(rx - lx, 0.0f), h = fmaxf(ry - ly, 0.0f);
                float inter = __fmul_rn(w, h);
                float uni = __fsub_rn(__fadd_rn(a, ap0), inter);
                if (__fmul_rn(inter, bU0) > __fmul_rn(bI0, uni)) {
                    bI0 = inter; bU0 = uni; bx0 = m;
                }
            }
            {
                float lx = fmaxf(gb.x, p1.x), ly = fmaxf(gb.y, p1.y);
                float rx = fminf(gb.z, p1.z), ry = fminf(gb.w, p1.w);
                float w = fmaxf(rx - lx, 0.0f), h = fmaxf(ry - ly, 0.0f);
                float inter = __fmul_rn(w, h);
                float uni = __fsub_rn(__fadd_rn(a, ap1), inter);
                if (__fmul_rn(inter, bU1) > __fmul_rn(bI1, uni)) {
                    bI1 = inter; bU1 = uni; bx1 = m;
                }
            }
        }

        float v0 = __fdiv_rn(bI0, bU0);
        float v1 = __fdiv_rn(bI1, bU1);
        mv[n0] = v0;  mi[n0] = (float)bx0;
        mv[n1] = v1;  mi[n1] = (float)bx1;
        bool fg0 = (v0 >= 0.5f);
        bool fg1 = (v1 >= 0.5f);
        unsigned u0 = f2s(pr0), u1 = f2s(pr1);
        unsigned bn0 = (unsigned)(pr0 * 256.0f); if (bn0 > 255u) bn0 = 255u;
        unsigned bn1 = (unsigned)(pr1 * 256.0f); if (bn1 > 255u) bn1 = 255u;
        g_keyFg[n0] = fg0 ? u0 : 0u;
        g_keyBg[n0] = fg0 ? 0u : u0;
        g_keyFg[n1] = fg1 ? u1 : 0u;
        g_keyBg[n1] = fg1 ? 0u : u1;
        atomicAdd(&g_hist[(fg0 ? 0 : 1) * BB * NBINS + b * NBINS + bn0], 1u);
        atomicAdd(&g_hist[(fg1 ? 0 : 1) * BB * NBINS + b * NBINS + bn1], 1u);
    }

    // ===================== Phase 2: grid barrier ============================
    // 256 CTAs, >=2 resident/SM guaranteed on 148 SMs => all resident.
    __syncthreads();
    if (tid == 0) {
        __threadfence();
        unsigned old = atomicAdd(&g_arrive, 1u);
        unsigned target = ((old >> 8) + 1u) << 8;   // this launch's 256 arrivals
        while (atomicAdd(&g_arrive, 0u) < target) {}
        __threadfence();
    }
    __syncthreads();

    // ===================== Phase 3: sample (CTAs 0..31) =====================
    if (c >= 32) return;

    const int  b      = c & 15;
    const bool wantFg = (c < 16);
    const int  K      = wantFg ? NFG : NBG;
    const int  off    = wantFg ? 0   : NFG;

    const unsigned* keys = (wantFg ? g_keyFg : g_keyBg) + b * NN;
    unsigned* histSlice = &g_hist[(wantFg ? 0 : 1) * BB * NBINS + b * NBINS];

    if (tid == 0) listCnt = 0;

    // Warp 0: suffix-scan histogram -> threshold bin T, total count
    if (wid == 0) {
        unsigned h[8];
#pragma unroll
        for (int e = 0; e < 8; ++e) h[e] = histSlice[lane * 8 + e];
        unsigned lsum = 0;
#pragma unroll
        for (int e = 0; e < 8; ++e) lsum += h[e];
        unsigned s = lsum;
#pragma unroll
        for (int d = 1; d < 32; d <<= 1) {
            unsigned v = __shfl_down_sync(0xffffffffu, s, d);
            if (lane + d < 32) s += v;
        }
        unsigned total = __shfl_sync(0xffffffffu, s, 0);
        unsigned run = s - lsum;                 // suffix over lanes > lane
        int myT = 0;
#pragma unroll
        for (int e = 7; e >= 0; --e) {
            unsigned sufE = run + h[e];
            if ((int)sufE >= K && (int)run < K) myT = lane * 8 + e;
            run = sufE;
        }
#pragma unroll
        for (int d = 1; d < 32; d <<= 1) {
            int v = __shfl_xor_sync(0xffffffffu, myT, d);
            if (v > myT) myT = v;
        }
        if (lane == 0) { sh_T = myT; sh_total = (int)total; }
    }
    __syncthreads();

    const int T = sh_T;
    const int total = sh_total;
    const uint4* k4 = (const uint4*)(keys + tid * 32);

    // Pass A: stream keys; build take-mask + zero-mask
    unsigned takemask = 0, zeromask = 0;
    {
#pragma unroll
        for (int e8 = 0; e8 < 8; ++e8) {
            uint4 a = k4[e8];
            unsigned uu[4] = {a.x, a.y, a.z, a.w};
#pragma unroll
            for (int v = 0; v < 4; ++v) {
                int e = e8 * 4 + v;
                unsigned ue = uu[v];
                if (ue == 0u) zeromask |= 1u << e;
                else {
                    float p = __uint_as_float(ue ^ 0x80000000u);
                    unsigned bn = (unsigned)(p * 256.0f); if (bn > 255u) bn = 255u;
                    if ((int)bn >= T) takemask |= 1u << e;
                }
            }
        }
    }

    // Compaction: one atomic per warp, then re-stream keys for values
    {
        unsigned cnt = 0;
        unsigned ballv[32];
#pragma unroll
        for (int e = 0; e < 32; ++e) {
            ballv[e] = __ballot_sync(0xffffffffu, (takemask >> e) & 1u);
            cnt += __popc(ballv[e]);
        }
        int base = 0;
        if (lane == 0 && cnt) base = atomicAdd(&listCnt, (int)cnt);
        base = __shfl_sync(0xffffffffu, base, 0);
        unsigned pre = 0;
        const unsigned lmask = (lane == 0) ? 0u : (0xffffffffu >> (32 - lane));
#pragma unroll
        for (int e8 = 0; e8 < 8; ++e8) {
            uint4 a = k4[e8];
            unsigned uu[4] = {a.x, a.y, a.z, a.w};
#pragma unroll
            for (int v = 0; v < 4; ++v) {
                int e = e8 * 4 + v;
                if ((takemask >> e) & 1u) {
                    int pos = base + (int)pre + __popc(ballv[e] & lmask);
                    if (pos < LISTCAP) {
                        int t = tid * 32 + e;
                        list[pos] = ((unsigned long long)uu[v] << 32) |
                                    (unsigned long long)(0xFFFFFFFFu - (unsigned)t);
                    }
                }
                pre += __popc(ballv[e]);
            }
        }
    }
    __syncthreads();

    // Exact ranking over ALL candidates
    {
        int S = listCnt < LISTCAP ? listCnt : LISTCAP;
        for (int i = tid; i < S; i += NTHR) {
            unsigned long long ki = list[i];
            int rank = 0;
            for (int j = 0; j < S; ++j) rank += (list[j] > ki);
            if (rank < K) {
                int idx = (int)(0xFFFFFFFFu - (unsigned)(ki & 0xFFFFFFFFull));
                int midx = (int)mi[b * NN + idx];
                s_idx[b * SAMP + off + rank] = (float)idx;
                s_gt [b * SAMP + off + rank] = (float)midx;
                s_cls[b * SAMP + off + rank] = wantFg ? (float)gtc[b * MM + midx] : 80.0f;
            }
        }
    }

    // Fill tail (total < K) with not-selected indices, ascending
    if (total < K) {
        const int need = K - total;
        int cc = __popc(zeromask);
        int inc = cc;
#pragma unroll
        for (int d = 1; d < 32; d <<= 1) {
            int v = __shfl_up_sync(0xffffffffu, inc, d);
            if (lane >= d) inc += v;
        }
        if (lane == 31) warpsum[wid] = (unsigned)inc;
        __syncthreads();
        if (wid == 0 && lane < 8) {
            int wv = (int)warpsum[lane];
            int winc = wv;
#pragma unroll
            for (int d = 1; d < 8; d <<= 1) {
                int v = __shfl_up_sync(0xffu, winc, d);
                if (lane >= d) winc += v;
            }
            warpsum[lane] = (unsigned)(winc - wv);
        }
        __syncthreads();
        int p = (int)warpsum[wid] + (inc - cc);
        const int base_e = tid * 32;
#pragma unroll
        for (int e = 0; e < 32; ++e) {
            if (zeromask & (1u << e)) {
                if (p < need) {
                    int slot = b * SAMP + off + total + p;
                    s_idx[slot] = (float)(base_e + e);
                    s_cls[slot] = -1.0f;
                    s_gt [slot] = -1.0f;
                }
                ++p;
            }
        }
    }
    __syncthreads();

    // Zero this block's histogram slice for the next graph replay
    if (tid < NBINS) histSlice[tid] = 0u;
}

extern "C" void kernel_launch(void* const* d_in, const int* in_sizes, int n_in,
                              void* d_out, int out_size) {
    const float* gt_boxes   = (const float*)d_in[0];   // [B,M,4]
    const int*   gt_classes = (const int*)  d_in[1];   // [B,M]
    const float* prop_boxes = (const float*)d_in[2];   // [B,N,4]
    const float* rand_pri   = (const float*)d_in[3];   // [B,N]

    float* out = (float*)d_out;
    float* matched_vals = out;                        // B*N
    float* matched_idxs = out + BB * NN;              // B*N
    float* sampled_idxs = out + 2 * BB * NN;          // B*512
    float* sampled_cls  = sampled_idxs + BB * SAMP;   // B*512
    float* sampled_gt   = sampled_cls  + BB * SAMP;   // B*512

    fused_kernel<<<NCTA, NTHR>>>((const float4*)gt_boxes,
                                 (const float4*)prop_boxes,
                                 rand_pri, gt_classes,
                                 matched_vals, matched_idxs,
                                 sampled_idxs, sampled_cls, sampled_gt);
}

// round 16
// speedup vs baseline: 1.6360x; 1.0007x over previous
#include <cuda_runtime.h>
#include <cuda_bf16.h>

#define BB    16
#define MM    256
#define NN    8192
#define NFG   128
#define NBG   384
#define SAMP  512
#define NBINS 256
#define BCAP  128
#define LISTCAP 2048
#define NCTA  512
#define NTHR  256

__device__ unsigned long long g_bucket[2 * BB * NBINS * BCAP];  // 8 MB
__device__ unsigned g_bcnt[2 * BB * NBINS];    // bin counters; zeroed by sampler
__device__ unsigned g_fgmask[BB * (NN / 32)];  // fg bitmask per batch
__device__ unsigned g_arrive;                  // monotone grid-barrier counter

static __device__ __forceinline__ unsigned f2s(float f) {
    unsigned u = __float_as_uint(f);
    return (u & 0x80000000u) ? ~u : (u | 0x80000000u);
}

__global__ __launch_bounds__(NTHR, 4)
void fused_kernel(const float4* __restrict__ gt,
                  const float4* __restrict__ prop,
                  const float*  __restrict__ pri,
                  const int*    __restrict__ gtc,
                  float* __restrict__ mv,
                  float* __restrict__ mi,
                  float* __restrict__ s_idx,
                  float* __restrict__ s_cls,
                  float* __restrict__ s_gt) {
    __shared__ float4 g[MM];
    __shared__ float  ga[MM];
    __shared__ unsigned long long list[LISTCAP];
    __shared__ unsigned shcnt[NBINS];
    __shared__ unsigned warpsum[8];
    __shared__ int sh_T, sh_total;

    const int tid = threadIdx.x;                 // 256
    const int c   = blockIdx.x;                  // 512
    const int lane = tid & 31;
    const int wid  = tid >> 5;
    const int b    = c >> 5;                     // batch
    const int q    = c & 31;                     // 256-proposal slice

    // ======== Phase 1: match (32 CTAs per batch, 1 proposal/thread) =========
    {
        {
            float4 v = gt[b * MM + tid];
            g[tid] = v;
            ga[tid] = __fmul_rn(v.z - v.x, v.w - v.y);
        }
        __syncthreads();

        const int nl = q * 256 + tid;            // local proposal index
        const int n0 = b * NN + nl;
        float4 p0 = prop[n0];
        float pr0 = pri[n0];
        float ap0 = __fmul_rn(p0.z - p0.x, p0.w - p0.y);

        float bI = -1.0f, bU = 1.0f;
        int bx = 0;

#pragma unroll 4
        for (int m = 0; m < MM; ++m) {
            float4 gb = g[m];
            float a = ga[m];
            float lx = fmaxf(gb.x, p0.x), ly = fmaxf(gb.y, p0.y);
            float rx = fminf(gb.z, p0.z), ry = fminf(gb.w, p0.w);
            float w = fmaxf(rx - lx, 0.0f);
            float h = ry - ly;                    // unclamped: inter<=0 if no overlap
            float inter = __fmul_rn(w, h);
            float uni = __fsub_rn(__fadd_rn(a, ap0), inter);
            if (__fmul_rn(inter, bU) > __fmul_rn(bI, uni)) {
                bI = inter; bU = uni; bx = m;
            }
        }

        float v0 = __fdiv_rn(bI, bU);
        mv[n0] = v0;
        mi[n0] = (float)bx;
        bool fg0 = (v0 >= 0.5f);
        unsigned u0 = f2s(pr0);
        unsigned bn0 = (unsigned)(pr0 * 256.0f); if (bn0 > 255u) bn0 = 255u;

        // bucket scatter
        int slice = (fg0 ? 0 : 1) * BB + b;
        unsigned pos = atomicAdd(&g_bcnt[slice * NBINS + bn0], 1u);
        if (pos < BCAP)
            g_bucket[(slice * NBINS + bn0) * BCAP + pos] =
                ((unsigned long long)u0 << 32) |
                (unsigned long long)(0xFFFFFFFFu - (unsigned)nl);

        // fg bitmask (1 word per warp)
        unsigned ball = __ballot_sync(0xffffffffu, fg0);
        if (lane == 0) g_fgmask[b * (NN / 32) + q * 8 + wid] = ball;
    }

    // ===================== Phase 2: grid barrier ============================
    __syncthreads();
    if (tid == 0) {
        __threadfence();
        unsigned old = atomicAdd(&g_arrive, 1u);
        unsigned target = ((old >> 9) + 1u) << 9;   // this launch's 512 arrivals
        while (atomicAdd(&g_arrive, 0u) < target) {}
        __threadfence();
    }
    __syncthreads();

    // ===================== Phase 3: sample (CTAs 0..31) =====================
    if (c >= 32) return;

    const int  sb     = c & 15;
    const bool wantFg = (c < 16);
    const int  K      = wantFg ? NFG : NBG;
    const int  off    = wantFg ? 0   : NFG;
    const int  slice  = (wantFg ? 0 : 1) * BB + sb;
    unsigned* cnts = &g_bcnt[slice * NBINS];

    // counts to smem (and zero global for next replay)
    if (tid < NBINS) {
        shcnt[tid] = cnts[tid];
        cnts[tid] = 0u;
    }
    __syncthreads();

    // Warp 0: suffix-scan counts -> threshold bin T, total
    if (wid == 0) {
        unsigned h[8];
#pragma unroll
        for (int e = 0; e < 8; ++e) h[e] = shcnt[lane * 8 + e];
        unsigned lsum = 0;
#pragma unroll
        for (int e = 0; e < 8; ++e) lsum += h[e];
        unsigned s = lsum;
#pragma unroll
        for (int d = 1; d < 32; d <<= 1) {
            unsigned v = __shfl_down_sync(0xffffffffu, s, d);
            if (lane + d < 32) s += v;
        }
        unsigned total = __shfl_sync(0xffffffffu, s, 0);
        unsigned run = s - lsum;
        int myT = 0;
#pragma unroll
        for (int e = 7; e >= 0; --e) {
            unsigned sufE = run + h[e];
            if ((int)sufE >= K && (int)run < K) myT = lane * 8 + e;
            run = sufE;
        }
#pragma unroll
        for (int d = 1; d < 32; d <<= 1) {
            int v = __shfl_xor_sync(0xffffffffu, myT, d);
            if (v > myT) myT = v;
        }
        if (lane == 0) { sh_T = myT; sh_total = (int)total; }
    }
    __syncthreads();

    const int T = sh_T;
    const int total = sh_total;

    // Gather candidate bins (>= T) into smem list
    int base = 0;
    for (int bn = 255; bn >= T && base < LISTCAP; --bn) {
        int cnt = (int)shcnt[bn];
        if (cnt > BCAP) cnt = BCAP;
        const unsigned long long* bk = &g_bucket[(slice * NBINS + bn) * BCAP];
        for (int i = tid; i < cnt; i += NTHR) {
            int pos = base + i;
            if (pos < LISTCAP) list[pos] = bk[i];
        }
        base += cnt;
    }
    int S = base < LISTCAP ? base : LISTCAP;
    __syncthreads();

    // Exact ranking over all candidates
    for (int i = tid; i < S; i += NTHR) {
        unsigned long long ki = list[i];
        int rank = 0;
        for (int j = 0; j < S; ++j) rank += (list[j] > ki);
        if (rank < K) {
            int idx = (int)(0xFFFFFFFFu - (unsigned)(ki & 0xFFFFFFFFull));
            int midx = (int)mi[sb * NN + idx];
            s_idx[sb * SAMP + off + rank] = (float)idx;
            s_gt [sb * SAMP + off + rank] = (float)midx;
            s_cls[sb * SAMP + off + rank] = wantFg ? (float)gtc[sb * MM + midx] : 80.0f;
        }
    }

    // Fill tail (total < K) with not-selected indices, ascending (from bitmask)
    if (total < K) {
        const int need = K - total;
        unsigned fgw = g_fgmask[sb * (NN / 32) + tid];   // word tid: n in [tid*32, tid*32+32)
        unsigned zeromask = wantFg ? ~fgw : fgw;         // "not selected on this side"
        int cc = __popc(zeromask);
        int inc = cc;
#pragma unroll
        for (int d = 1; d < 32; d <<= 1) {
            int v = __shfl_up_sync(0xffffffffu, inc, d);
            if (lane >= d) inc += v;
        }
        if (lane == 31) warpsum[wid] = (unsigned)inc;
        __syncthreads();
        if (wid == 0 && lane < 8) {
            int wv = (int)warpsum[lane];
            int winc = wv;
#pragma unroll
            for (int d = 1; d < 8; d <<= 1) {
                int v = __shfl_up_sync(0xffu, winc, d);
                if (lane >= d) winc += v;
            }
            warpsum[lane] = (unsigned)(winc - wv);
        }
        __syncthreads();
        int p = (int)warpsum[wid] + (inc - cc);
        const int base_e = tid * 32;
        for (int e = 0; e < 32; ++e) {
            if (zeromask & (1u << e)) {
                if (p < need) {
                    int slot = sb * SAMP + off + total + p;
                    s_idx[slot] = (float)(base_e + e);
                    s_cls[slot] = -1.0f;
                    s_gt [slot] = -1.0f;
                }
                ++p;
            }
        }
    }
}

extern "C" void kernel_launch(void* const* d_in, const int* in_sizes, int n_in,
                              void* d_out, int out_size) {
    const float* gt_boxes   = (const float*)d_in[0];   // [B,M,4]
    const int*   gt_classes = (const int*)  d_in[1];   // [B,M]
    const float* prop_boxes = (const float*)d_in[2];   // [B,N,4]
    const float* rand_pri   = (const float*)d_in[3];   // [B,N]

    float* out = (float*)d_out;
    float* matched_vals = out;                        // B*N
    float* matched_idxs = out + BB * NN;              // B*N
    float* sampled_idxs = out + 2 * BB * NN;          // B*512
    float* sampled_cls  = sampled_idxs + BB * SAMP;   // B*512
    float* sampled_gt   = sampled_cls  + BB * SAMP;   // B*512

    fused_kernel<<<NCTA, NTHR>>>((const float4*)gt_boxes,
                                 (const float4*)prop_boxes,
                                 rand_pri, gt_classes,
                                 matched_vals, matched_idxs,
                                 sampled_idxs, sampled_cls, sampled_gt);
}

// round 17
// speedup vs baseline: 1.7130x; 1.0471x over previous
#include <cuda_runtime.h>
#include <cuda_bf16.h>

#define BB    16
#define MM    256
#define NN    8192
#define NFG   128
#define NBG   384
#define SAMP  512
#define NBINS 256
#define LISTCAP 2048
#define NMATCH 512
#define NSAMP  32
#define NCTA  (NMATCH + NSAMP)
#define NTHR  256

__device__ unsigned g_keyFg[BB * NN];          // f2s(pri) if fg else 0
__device__ unsigned g_keyBg[BB * NN];          // f2s(pri) if bg else 0
__device__ unsigned g_hist[2 * BB * NBINS];    // [side][b][bin]; zeroed by sampler
__device__ unsigned g_cnt[BB];                 // per-batch matcher arrivals (monotone)
__device__ unsigned g_sepoch[NSAMP];           // per-sampler-CTA epoch (monotone)

static __device__ __forceinline__ unsigned f2s(float f) {
    unsigned u = __float_as_uint(f);
    return (u & 0x80000000u) ? ~u : (u | 0x80000000u);
}

__global__ __launch_bounds__(NTHR, 4)
void fused_kernel(const float4* __restrict__ gt,
                  const float4* __restrict__ prop,
                  const float*  __restrict__ pri,
                  const int*    __restrict__ gtc,
                  float* __restrict__ mv,
                  float* __restrict__ mi,
                  float* __restrict__ s_idx,
                  float* __restrict__ s_cls,
                  float* __restrict__ s_gt) {
    __shared__ float4 g[MM];
    __shared__ float  ga[MM];
    __shared__ unsigned long long list[LISTCAP];
    __shared__ unsigned warpsum[8];
    __shared__ int listCnt, sh_T, sh_total;

    const int tid = threadIdx.x;                 // 256
    const int c   = blockIdx.x;                  // 544
    const int lane = tid & 31;
    const int wid  = tid >> 5;

    if (c < NMATCH) {
        // ====== Matcher CTA: 32 per batch, 1 proposal/thread (R11 exact) =====
        const int b = c >> 5;
        const int q = c & 31;
        {
            float4 v = gt[b * MM + tid];
            g[tid] = v;
            ga[tid] = __fmul_rn(v.z - v.x, v.w - v.y);
        }
        __syncthreads();

        const int n0 = b * NN + q * 256 + tid;
        float4 p0 = prop[n0];
        float pr0 = pri[n0];
        float ap0 = __fmul_rn(p0.z - p0.x, p0.w - p0.y);

        float bI = -1.0f, bU = 1.0f;
        int bx = 0;

#pragma unroll 4
        for (int m = 0; m < MM; ++m) {
            float4 gb = g[m];
            float a = ga[m];
            float lx = fmaxf(gb.x, p0.x), ly = fmaxf(gb.y, p0.y);
            float rx = fminf(gb.z, p0.z), ry = fminf(gb.w, p0.w);
            float w = fmaxf(rx - lx, 0.0f), h = fmaxf(ry - ly, 0.0f);
            float inter = __fmul_rn(w, h);
            float uni = __fsub_rn(__fadd_rn(a, ap0), inter);
            if (__fmul_rn(inter, bU) > __fmul_rn(bI, uni)) {
                bI = inter; bU = uni; bx = m;
            }
        }

        float v0 = __fdiv_rn(bI, bU);
        mv[n0] = v0;
        mi[n0] = (float)bx;
        bool fg0 = (v0 >= 0.5f);
        unsigned u0 = f2s(pr0);
        unsigned bn0 = (unsigned)(pr0 * 256.0f); if (bn0 > 255u) bn0 = 255u;
        g_keyFg[n0] = fg0 ? u0 : 0u;
        g_keyBg[n0] = fg0 ? 0u : u0;
        atomicAdd(&g_hist[(fg0 ? 0 : 1) * BB * NBINS + b * NBINS + bn0], 1u);

        // signal completion (release) and exit — no barrier
        __syncthreads();
        if (tid == 0) {
            __threadfence();
            atomicAdd(&g_cnt[b], 1u);
        }
        return;
    }

    // ================= Sampler CTA: one (batch, side) each ==================
    const int  i      = c - NMATCH;              // 0..31
    const int  b      = i & 15;
    const bool wantFg = (i < 16);
    const int  K      = wantFg ? NFG : NBG;
    const int  off    = wantFg ? 0   : NFG;

    // Wait for this batch's 32 matchers. Epoch from private monotone counter
    // (only this CTA writes it) => graph-replay safe.
    if (tid == 0) {
        unsigned epoch = g_sepoch[i] + 1u;
        g_sepoch[i] = epoch;
        unsigned target = epoch * 32u;
        while (atomicAdd(&g_cnt[b], 0u) < target) { __nanosleep(128); }
        __threadfence();                          // acquire matchers' writes
    }
    __syncthreads();

    const unsigned* keys = (wantFg ? g_keyFg : g_keyBg) + b * NN;
    unsigned* histSlice = &g_hist[(wantFg ? 0 : 1) * BB * NBINS + b * NBINS];

    if (tid == 0) listCnt = 0;

    // Warp 0: suffix-scan histogram -> threshold bin T, total count
    if (wid == 0) {
        unsigned h[8];
#pragma unroll
        for (int e = 0; e < 8; ++e) h[e] = histSlice[lane * 8 + e];
#pragma unroll
        for (int e = 0; e < 8; ++e) histSlice[lane * 8 + e] = 0u;  // next replay
        unsigned lsum = 0;
#pragma unroll
        for (int e = 0; e < 8; ++e) lsum += h[e];
        unsigned s = lsum;
#pragma unroll
        for (int d = 1; d < 32; d <<= 1) {
            unsigned v = __shfl_down_sync(0xffffffffu, s, d);
            if (lane + d < 32) s += v;
        }
        unsigned total = __shfl_sync(0xffffffffu, s, 0);
        unsigned run = s - lsum;                 // suffix over lanes > lane
        int myT = 0;
#pragma unroll
        for (int e = 7; e >= 0; --e) {
            unsigned sufE = run + h[e];
            if ((int)sufE >= K && (int)run < K) myT = lane * 8 + e;
            run = sufE;
        }
#pragma unroll
        for (int d = 1; d < 32; d <<= 1) {
            int v = __shfl_xor_sync(0xffffffffu, myT, d);
            if (v > myT) myT = v;
        }
        if (lane == 0) { sh_T = myT; sh_total = (int)total; }
    }
    __syncthreads();

    const int T = sh_T;
    const int total = sh_total;
    const uint4* k4 = (const uint4*)(keys + tid * 32);

    // Pass A: stream keys; build take-mask + zero-mask
    unsigned takemask = 0, zeromask = 0;
    {
#pragma unroll
        for (int e8 = 0; e8 < 8; ++e8) {
            uint4 a = k4[e8];
            unsigned uu[4] = {a.x, a.y, a.z, a.w};
#pragma unroll
            for (int v = 0; v < 4; ++v) {
                int e = e8 * 4 + v;
                unsigned ue = uu[v];
                if (ue == 0u) zeromask |= 1u << e;
                else {
                    float p = __uint_as_float(ue ^ 0x80000000u);
                    unsigned bn = (unsigned)(p * 256.0f); if (bn > 255u) bn = 255u;
                    if ((int)bn >= T) takemask |= 1u << e;
                }
            }
        }
    }

    // Compaction: one atomic per warp, then re-stream keys for values
    {
        unsigned cnt = 0;
        unsigned ballv[32];
#pragma unroll
        for (int e = 0; e < 32; ++e) {
            ballv[e] = __ballot_sync(0xffffffffu, (takemask >> e) & 1u);
            cnt += __popc(ballv[e]);
        }
        int base = 0;
        if (lane == 0 && cnt) base = atomicAdd(&listCnt, (int)cnt);
        base = __shfl_sync(0xffffffffu, base, 0);
        unsigned pre = 0;
        const unsigned lmask = (lane == 0) ? 0u : (0xffffffffu >> (32 - lane));
#pragma unroll
        for (int e8 = 0; e8 < 8; ++e8) {
            uint4 a = k4[e8];
            unsigned uu[4] = {a.x, a.y, a.z, a.w};
#pragma unroll
            for (int v = 0; v < 4; ++v) {
                int e = e8 * 4 + v;
                if ((takemask >> e) & 1u) {
                    int pos = base + (int)pre + __popc(ballv[e] & lmask);
                    if (pos < LISTCAP) {
                        int t = tid * 32 + e;
                        list[pos] = ((unsigned long long)uu[v] << 32) |
                                    (unsigned long long)(0xFFFFFFFFu - (unsigned)t);
                    }
                }
                pre += __popc(ballv[e]);
            }
        }
    }
    __syncthreads();

    // Exact ranking over ALL candidates
    {
        int S = listCnt < LISTCAP ? listCnt : LISTCAP;
        for (int i2 = tid; i2 < S; i2 += NTHR) {
            unsigned long long ki = list[i2];
            int rank = 0;
            for (int j = 0; j < S; ++j) rank += (list[j] > ki);
            if (rank < K) {
                int idx = (int)(0xFFFFFFFFu - (unsigned)(ki & 0xFFFFFFFFull));
                int midx = (int)mi[b * NN + idx];
                s_idx[b * SAMP + off + rank] = (float)idx;
                s_gt [b * SAMP + off + rank] = (float)midx;
                s_cls[b * SAMP + off + rank] = wantFg ? (float)gtc[b * MM + midx] : 80.0f;
            }
        }
    }

    // Fill tail (total < K) with not-selected indices, ascending
    if (total < K) {
        const int need = K - total;
        int cc = __popc(zeromask);
        int inc = cc;
#pragma unroll
        for (int d = 1; d < 32; d <<= 1) {
            int v = __shfl_up_sync(0xffffffffu, inc, d);
            if (lane >= d) inc += v;
        }
        if (lane == 31) warpsum[wid] = (unsigned)inc;
        __syncthreads();
        if (wid == 0 && lane < 8) {
            int wv = (int)warpsum[lane];
            int winc = wv;
#pragma unroll
            for (int d = 1; d < 8; d <<= 1) {
                int v = __shfl_up_sync(0xffu, winc, d);
                if (lane >= d) winc += v;
            }
            warpsum[lane] = (unsigned)(winc - wv);
        }
        __syncthreads();
        int p = (int)warpsum[wid] + (inc - cc);
        const int base_e = tid * 32;
#pragma unroll
        for (int e = 0; e < 32; ++e) {
            if (zeromask & (1u << e)) {
                if (p < need) {
                    int slot = b * SAMP + off + total + p;
                    s_idx[slot] = (float)(base_e + e);
                    s_cls[slot] = -1.0f;
                    s_gt [slot] = -1.0f;
                }
                ++p;
            }
        }
    }
}

extern "C" void kernel_launch(void* const* d_in, const int* in_sizes, int n_in,
                              void* d_out, int out_size) {
    const float* gt_boxes   = (const float*)d_in[0];   // [B,M,4]
    const int*   gt_classes = (const int*)  d_in[1];   // [B,M]
    const float* prop_boxes = (const float*)d_in[2];   // [B,N,4]
    const float* rand_pri   = (const float*)d_in[3];   // [B,N]

    float* out = (float*)d_out;
    float* matched_vals = out;                        // B*N
    float* matched_idxs = out + BB * NN;              // B*N
    float* sampled_idxs = out + 2 * BB * NN;          // B*512
    float* sampled_cls  = sampled_idxs + BB * SAMP;   // B*512
    float* sampled_gt   = sampled_cls  + BB * SAMP;   // B*512

    fused_kernel<<<NCTA, NTHR>>>((const float4*)gt_boxes,
                                 (const float4*)prop_boxes,
                                 rand_pri, gt_classes,
                                 matched_vals, matched_idxs,
                                 sampled_idxs, sampled_cls, sampled_gt);
}